// round 5
// baseline (speedup 1.0000x reference)
#include <cuda_runtime.h>
#include <cstdint>

// Problem constants (fixed by the reference: N=64, T=2048, F=256)
#define CBS_N 64
#define CBS_T 2048
#define CBS_F 256
#define CBS_F4 (CBS_F / 4)     // 64 float4 per (n, t) row
#define V_PER_THREAD 4          // 4 float4 = 64B per thread
#define THREADS_PER_ROW (CBS_F4 / V_PER_THREAD)  // 16
#define ROWS_PER_BLOCK (256 / THREADS_PER_ROW)   // 16

// Findings:
//  - slices/lens are int32 (JAX x64 disabled); chunk_lens compared as f32.
//  - R4: fused kernel at 26.6us was issue/ALU-bound (issue 50.6%, alu 32.1%,
//    DRAM only 49.6%). One float4 per thread left too little MLP and too
//    much index math per byte. This version: 64B (4x float4) per thread.

__device__ __forceinline__ int imax_(int a, int b) { return a > b ? a : b; }
__device__ __forceinline__ int imin_(int a, int b) { return a < b ? a : b; }

// grid = (T/ROWS_PER_BLOCK, N) = (128, 64), block = 256.
// Each thread handles 4 consecutive float4 (64B) of one (n, t) row.
__global__ void chunk_by_slices_v2_kernel(const float4* __restrict__ x,
                                          const int* __restrict__ slices,
                                          const int* __restrict__ lens,
                                          float4* __restrict__ out,
                                          float* __restrict__ out_lens) {
    const int n = blockIdx.y;

    // Per-row parameters; uniform across the block -> L1 broadcast.
    const int s = slices[2 * n];
    const int e = slices[2 * n + 1];
    const int chunk_len = imax_(e - s, 0);
    const int left_pad  = (chunk_len == 0) ? 0 : imax_(-s, 0);
    const int start_    = imax_(s, 0);
    const int end_      = imin_(e, lens[n]);
    const int slice_len = imax_(end_ - start_, 0);

    // Fused chunk_lens write: one thread per n.
    if (blockIdx.x == 0 && threadIdx.x == 0) {
        out_lens[n] = (float)chunk_len;
    }

    const int t = blockIdx.x * ROWS_PER_BLOCK + (threadIdx.x >> 4);  // /16
    const int f = (threadIdx.x & 15) * V_PER_THREAD;                  // 0..60 step 4

    const bool valid = (t >= left_pad) && (t < left_pad + slice_len);

    int src = start_ + t - left_pad;
    src = imin_(imax_(src, 0), CBS_T - 1);

    float4 v0, v1, v2, v3;
    if (valid) {
        const float4* xr = &x[(n * CBS_T + src) * CBS_F4 + f];
        v0 = __ldg(xr + 0);
        v1 = __ldg(xr + 1);
        v2 = __ldg(xr + 2);
        v3 = __ldg(xr + 3);
    } else {
        v0 = v1 = v2 = v3 = make_float4(0.f, 0.f, 0.f, 0.f);
    }

    float4* op = &out[(n * CBS_T + t) * CBS_F4 + f];
    __stcs(op + 0, v0);
    __stcs(op + 1, v1);
    __stcs(op + 2, v2);
    __stcs(op + 3, v3);
}

extern "C" void kernel_launch(void* const* d_in, const int* in_sizes, int n_in,
                              void* d_out, int out_size) {
    const float4* x      = (const float4*)d_in[0];
    const int*    slices = (const int*)d_in[1];
    const int*    lens   = (const int*)d_in[2];
    float4*       out    = (float4*)d_out;

    const long long chunks_elems = (long long)CBS_N * CBS_T * CBS_F;
    float* out_lens = ((float*)d_out) + chunks_elems;

    dim3 block(256);
    dim3 grid(CBS_T / ROWS_PER_BLOCK, CBS_N);  // (128, 64)
    chunk_by_slices_v2_kernel<<<grid, block>>>(x, slices, lens, out, out_lens);
}

// round 6
// speedup vs baseline: 1.4334x; 1.4334x over previous
#include <cuda_runtime.h>
#include <cstdint>

// Problem constants (fixed by the reference: N=64, T=2048, F=256)
#define CBS_N 64
#define CBS_T 2048
#define CBS_F 256
#define CBS_F4 (CBS_F / 4)     // 64 float4 per (n, t) row
#define THREADS_PER_ROW 16      // each thread: 4 float4, INTERLEAVED stride 16
#define ROWS_PER_BLOCK (256 / THREADS_PER_ROW)   // 16

// Findings:
//  - slices/lens int32; chunk_lens written as float32.
//  - R4 (1 float4/thread): 26.6us, issue 50.6% / alu 32.1%, DRAM 49.6%.
//  - R5 (4 CONSECUTIVE float4/thread): 39.3us — lanes strided 64B inside
//    each LDG/STG -> 4x L1tex wavefronts (L1 73%), DRAM fell to 36%.
//  - This version: 4 float4/thread but INTERLEAVED (f = lane + 16k) so
//    every memory instruction is dense across the warp. Keeps the low
//    issue/ALU cost of R5 with the coalescing of R4.

__device__ __forceinline__ int imax_(int a, int b) { return a > b ? a : b; }
__device__ __forceinline__ int imin_(int a, int b) { return a < b ? a : b; }

// grid = (T/16, N) = (128, 64), block = 256.
__global__ void chunk_by_slices_v3_kernel(const float4* __restrict__ x,
                                          const int* __restrict__ slices,
                                          const int* __restrict__ lens,
                                          float4* __restrict__ out,
                                          float* __restrict__ out_lens) {
    const int n = blockIdx.y;

    // Per-row parameters; uniform across the block -> L1 broadcast.
    const int s = slices[2 * n];
    const int e = slices[2 * n + 1];
    const int chunk_len = imax_(e - s, 0);
    const int left_pad  = (chunk_len == 0) ? 0 : imax_(-s, 0);
    const int start_    = imax_(s, 0);
    const int end_      = imin_(e, lens[n]);
    const int slice_len = imax_(end_ - start_, 0);

    // Fused chunk_lens write: one thread per n.
    if (blockIdx.x == 0 && threadIdx.x == 0) {
        out_lens[n] = (float)chunk_len;
    }

    const int t  = blockIdx.x * ROWS_PER_BLOCK + (threadIdx.x >> 4);
    const int f0 = threadIdx.x & 15;   // interleaved: f0, f0+16, f0+32, f0+48

    const bool valid = (t >= left_pad) && (t < left_pad + slice_len);

    int src = start_ + t - left_pad;
    src = imin_(imax_(src, 0), CBS_T - 1);

    float4 v0, v1, v2, v3;
    if (valid) {
        const float4* xr = &x[(n * CBS_T + src) * CBS_F4 + f0];
        v0 = __ldg(xr + 0);
        v1 = __ldg(xr + 16);
        v2 = __ldg(xr + 32);
        v3 = __ldg(xr + 48);
    } else {
        v0 = v1 = v2 = v3 = make_float4(0.f, 0.f, 0.f, 0.f);
    }

    float4* op = &out[(n * CBS_T + t) * CBS_F4 + f0];
    __stcs(op + 0,  v0);
    __stcs(op + 16, v1);
    __stcs(op + 32, v2);
    __stcs(op + 48, v3);
}

extern "C" void kernel_launch(void* const* d_in, const int* in_sizes, int n_in,
                              void* d_out, int out_size) {
    const float4* x      = (const float4*)d_in[0];
    const int*    slices = (const int*)d_in[1];
    const int*    lens   = (const int*)d_in[2];
    float4*       out    = (float4*)d_out;

    const long long chunks_elems = (long long)CBS_N * CBS_T * CBS_F;
    float* out_lens = ((float*)d_out) + chunks_elems;

    dim3 block(256);
    dim3 grid(CBS_T / ROWS_PER_BLOCK, CBS_N);  // (128, 64)
    chunk_by_slices_v3_kernel<<<grid, block>>>(x, slices, lens, out, out_lens);
}